// round 3
// baseline (speedup 1.0000x reference)
#include <cuda_runtime.h>
#include <cuda_bf16.h>
#include <cstdint>

#define NMAX 50000
#define EMAX 600000
#define D 128

// ---------------- scratch (device globals; no runtime allocation) ------------
__device__ int   g_deg[4][NMAX];        // [0]=outdeg r0, [1]=indeg r0, [2]=outdeg r1, [3]=indeg r1
__device__ int   g_rowptr[2][NMAX + 1];
__device__ int   g_cursor[2][NMAX];
__device__ int   g_col[2][EMAX];
__device__ float g_srcscale[2][NMAX];
__device__ float g_Y[(size_t)NMAX * D];
__device__ float g_hA[(size_t)NMAX * D];
__device__ float g_hB[(size_t)NMAX * D];
__device__ float g_Hcat[(size_t)NMAX * 2 * D];
__device__ float g_H1[(size_t)NMAX * D];
__device__ float g_stats[2 * D];        // colsum, colsumsq
__device__ float g_aff[2 * D];          // a (scale), b (shift)

// ---------------- packed f32x2 helpers (Blackwell) ---------------------------
__device__ __forceinline__ unsigned long long pack2(float x, float y) {
    unsigned long long r;
    asm("mov.b64 %0, {%1, %2};" : "=l"(r) : "f"(x), "f"(y));
    return r;
}
__device__ __forceinline__ void ffma2(unsigned long long& d, unsigned long long a,
                                      unsigned long long b) {
    asm("fma.rn.f32x2 %0, %1, %2, %0;" : "+l"(d) : "l"(a), "l"(b));
}
__device__ __forceinline__ float2 unpack2(unsigned long long v) {
    float2 r;
    asm("mov.b64 {%0, %1}, %2;" : "=f"(r.x), "=f"(r.y) : "l"(v));
    return r;
}

// ---------------- graph build ------------------------------------------------
__global__ void k_zero(int n) {
    int i = blockIdx.x * blockDim.x + threadIdx.x;
    if (i < n) {
        g_deg[0][i] = 0; g_deg[1][i] = 0; g_deg[2][i] = 0; g_deg[3][i] = 0;
    }
    if (i < 2 * D) g_stats[i] = 0.0f;
}

__global__ void k_deg(const int* __restrict__ src, const int* __restrict__ dst,
                      int rel, int E) {
    int e = blockIdx.x * blockDim.x + threadIdx.x;
    if (e < E) {
        atomicAdd(&g_deg[rel * 2 + 0][src[e]], 1);
        atomicAdd(&g_deg[rel * 2 + 1][dst[e]], 1);
    }
}

// single-block exclusive scan of indeg -> rowptr (n up to NMAX)
__global__ void k_scan(int rel, int n) {
    __shared__ int sh[1024];
    __shared__ int carry;
    int t = threadIdx.x;
    const int* cnt = g_deg[rel * 2 + 1];
    int* rowptr = g_rowptr[rel];
    if (t == 0) carry = 0;
    __syncthreads();
    for (int base = 0; base < n; base += 1024) {
        int i = base + t;
        int v = (i < n) ? cnt[i] : 0;
        sh[t] = v;
        __syncthreads();
        for (int off = 1; off < 1024; off <<= 1) {
            int tv = (t >= off) ? sh[t - off] : 0;
            __syncthreads();
            sh[t] += tv;
            __syncthreads();
        }
        int incl = sh[t];
        if (i < n) rowptr[i] = carry + incl - v;
        __syncthreads();
        if (t == 1023) carry += sh[1023];
        __syncthreads();
    }
    if (t == 0) rowptr[n] = carry;
}

__global__ void k_prep(int n) {
    int i = blockIdx.x * blockDim.x + threadIdx.x;
    if (i >= n) return;
#pragma unroll
    for (int rel = 0; rel < 2; ++rel) {
        int od = g_deg[rel * 2][i];
        g_srcscale[rel][i] = rsqrtf((float)(od > 0 ? od : 1));
        g_cursor[rel][i] = g_rowptr[rel][i];
    }
}

__global__ void k_fill(const int* __restrict__ src, const int* __restrict__ dst,
                       int rel, int E) {
    int e = blockIdx.x * blockDim.x + threadIdx.x;
    if (e < E) {
        int p = atomicAdd(&g_cursor[rel][dst[e]], 1);
        g_col[rel][p] = src[e];
    }
}

// ---------------- aggregation: out[dst] = relu?( rsqrt(din)*sum_e s[src]*Y[src] + b )
__global__ void k_agg(const float* __restrict__ Y, int rel,
                      const float* __restrict__ bias, float* __restrict__ out,
                      int n, int ldc, int relu) {
    int warp = (blockIdx.x * blockDim.x + threadIdx.x) >> 5;
    int lane = threadIdx.x & 31;
    if (warp >= n) return;
    const int* __restrict__ rowptr = g_rowptr[rel];
    const int* __restrict__ col = g_col[rel];
    const float* __restrict__ ss = g_srcscale[rel];
    int s = rowptr[warp], e = rowptr[warp + 1];
    float4 acc = make_float4(0.f, 0.f, 0.f, 0.f);
    const float4* Y4 = (const float4*)Y;
    for (int i = s; i < e; ++i) {
        int src = __ldg(col + i);
        float w = __ldg(ss + src);
        float4 v = __ldg(Y4 + (size_t)src * 32 + lane);
        acc.x += w * v.x; acc.y += w * v.y; acc.z += w * v.z; acc.w += w * v.w;
    }
    int deg = e - s;
    float sc = rsqrtf((float)(deg > 0 ? deg : 1));
    float4 b = ((const float4*)bias)[lane];
    acc.x = acc.x * sc + b.x;
    acc.y = acc.y * sc + b.y;
    acc.z = acc.z * sc + b.z;
    acc.w = acc.w * sc + b.w;
    if (relu) {
        acc.x = fmaxf(acc.x, 0.f); acc.y = fmaxf(acc.y, 0.f);
        acc.z = fmaxf(acc.z, 0.f); acc.w = fmaxf(acc.w, 0.f);
    }
    *(float4*)(out + (size_t)warp * ldc + lane * 4) = acc;
}

// ---------------- GEMM: C[M,128] = A[M,K] @ W[K,128]  (fp32, f32x2 packed) ----
// block tile 128x128, 256 threads (16x16), per-thread 8x8, BK=16
__global__ __launch_bounds__(256) void k_gemm(const float* __restrict__ A,
                                              const float* __restrict__ W,
                                              float* __restrict__ C,
                                              int M, int K, int lda, int ldc) {
    __shared__ float As[16][128];   // transposed: As[k][m]
    __shared__ float Bs[16][128];   // Bs[k][n]
    int tid = threadIdx.x;
    int tx = tid & 15;      // col group
    int ty = tid >> 4;      // row group
    int rowBase = blockIdx.x * 128;

    unsigned long long acc[8][4];
#pragma unroll
    for (int r = 0; r < 8; ++r)
#pragma unroll
        for (int p = 0; p < 4; ++p) acc[r][p] = 0ull;

    for (int k0 = 0; k0 < K; k0 += 16) {
        // A tile: 128 rows x 16 k, as 512 float4 (row, 4k)
#pragma unroll
        for (int i = 0; i < 2; ++i) {
            int f4 = tid * 2 + i;          // 0..511
            int m = f4 >> 2;
            int kg = (f4 & 3) << 2;
            int gm = rowBase + m;
            float4 v = make_float4(0.f, 0.f, 0.f, 0.f);
            if (gm < M) v = *(const float4*)(A + (size_t)gm * lda + k0 + kg);
            As[kg + 0][m] = v.x; As[kg + 1][m] = v.y;
            As[kg + 2][m] = v.z; As[kg + 3][m] = v.w;
        }
        // B tile: 16 x 128 floats = 512 float4
#pragma unroll
        for (int i = 0; i < 2; ++i) {
            int f4 = tid * 2 + i;          // 0..511
            int kt = f4 >> 5;
            int n4 = (f4 & 31) << 2;
            float4 v = *(const float4*)(W + (size_t)(k0 + kt) * 128 + n4);
            *(float4*)&Bs[kt][n4] = v;
        }
        __syncthreads();
#pragma unroll
        for (int kk = 0; kk < 16; ++kk) {
            float a[8];
            *(float4*)(a + 0) = *(const float4*)&As[kk][ty * 8];
            *(float4*)(a + 4) = *(const float4*)&As[kk][ty * 8 + 4];
            float4 b0 = *(const float4*)&Bs[kk][tx * 8];
            float4 b1 = *(const float4*)&Bs[kk][tx * 8 + 4];
            unsigned long long bp[4];
            bp[0] = pack2(b0.x, b0.y); bp[1] = pack2(b0.z, b0.w);
            bp[2] = pack2(b1.x, b1.y); bp[3] = pack2(b1.z, b1.w);
#pragma unroll
            for (int r = 0; r < 8; ++r) {
                unsigned long long a2 = pack2(a[r], a[r]);
                ffma2(acc[r][0], a2, bp[0]);
                ffma2(acc[r][1], a2, bp[1]);
                ffma2(acc[r][2], a2, bp[2]);
                ffma2(acc[r][3], a2, bp[3]);
            }
        }
        __syncthreads();
    }

#pragma unroll
    for (int r = 0; r < 8; ++r) {
        int gm = rowBase + ty * 8 + r;
        if (gm < M) {
            float2 p0 = unpack2(acc[r][0]), p1 = unpack2(acc[r][1]);
            float2 p2 = unpack2(acc[r][2]), p3 = unpack2(acc[r][3]);
            float4 o0 = make_float4(p0.x, p0.y, p1.x, p1.y);
            float4 o1 = make_float4(p2.x, p2.y, p3.x, p3.y);
            *(float4*)(C + (size_t)gm * ldc + tx * 8)     = o0;
            *(float4*)(C + (size_t)gm * ldc + tx * 8 + 4) = o1;
        }
    }
}

// ---------------- BN stats / finalize / fused head ---------------------------
__global__ void k_bnstats(const float* __restrict__ H, int M) {
    int c = threadIdx.x;              // 128 threads, one column each
    int rows_per_block = (M + gridDim.x - 1) / gridDim.x;
    int r0 = blockIdx.x * rows_per_block;
    int r1 = r0 + rows_per_block; if (r1 > M) r1 = M;
    float s = 0.f, q = 0.f;
    for (int r = r0; r < r1; ++r) {
        float v = H[(size_t)r * D + c];
        s += v; q += v * v;
    }
    atomicAdd(&g_stats[c], s);
    atomicAdd(&g_stats[D + c], q);
}

__global__ void k_bnfinal(const float* __restrict__ gamma,
                          const float* __restrict__ beta, int M) {
    int c = threadIdx.x;
    float invM = 1.0f / (float)M;
    float mu = g_stats[c] * invM;
    float var = g_stats[D + c] * invM - mu * mu;
    float a = gamma[c] * rsqrtf(var + 1e-5f);
    g_aff[c] = a;
    g_aff[D + c] = beta[c] - mu * a;
}

__global__ void k_head(const float* __restrict__ H, const float* __restrict__ Wm2,
                       float* __restrict__ out, int n) {
    int warp = (blockIdx.x * blockDim.x + threadIdx.x) >> 5;
    int lane = threadIdx.x & 31;
    if (warp >= n) return;
    float4 h = ((const float4*)(H + (size_t)warp * D))[lane];
    float4 a = ((const float4*)g_aff)[lane];
    float4 b = ((const float4*)(g_aff + D))[lane];
    float v0 = fmaxf(h.x * a.x + b.x, 0.f);
    float v1 = fmaxf(h.y * a.y + b.y, 0.f);
    float v2 = fmaxf(h.z * a.z + b.z, 0.f);
    float v3 = fmaxf(h.w * a.w + b.w, 0.f);
    // Wm2 is [128][2] row-major; lane covers cols 4l..4l+3 -> 8 consecutive floats
    float4 wA = __ldg((const float4*)Wm2 + lane * 2 + 0); // {W[4l][0],W[4l][1],W[4l+1][0],W[4l+1][1]}
    float4 wB = __ldg((const float4*)Wm2 + lane * 2 + 1);
    float s0 = v0 * wA.x + v1 * wA.z + v2 * wB.x + v3 * wB.z;
    float s1 = v0 * wA.y + v1 * wA.w + v2 * wB.y + v3 * wB.w;
#pragma unroll
    for (int off = 16; off > 0; off >>= 1) {
        s0 += __shfl_down_sync(0xffffffffu, s0, off);
        s1 += __shfl_down_sync(0xffffffffu, s1, off);
    }
    if (lane == 0) {
        out[(size_t)warp * 2 + 0] = s0;
        out[(size_t)warp * 2 + 1] = s1;
    }
}

// ---------------- launch -----------------------------------------------------
extern "C" void kernel_launch(void* const* d_in, const int* in_sizes, int n_in,
                              void* d_out, int out_size) {
    const float* xA   = (const float*)d_in[0];
    const float* xB   = (const float*)d_in[1];
    const int* src0   = (const int*)d_in[2];
    const int* dst0   = (const int*)d_in[3];
    const int* src1   = (const int*)d_in[4];
    const int* dst1   = (const int*)d_in[5];
    const float* W1_0 = (const float*)d_in[6];
    const float* b1_0 = (const float*)d_in[7];
    const float* W1_1 = (const float*)d_in[8];
    const float* b1_1 = (const float*)d_in[9];
    const float* W2_0 = (const float*)d_in[10];
    const float* b2_0 = (const float*)d_in[11];
    const float* W2_1 = (const float*)d_in[12];
    const float* b2_1 = (const float*)d_in[13];
    const float* Wm1  = (const float*)d_in[14];
    const float* gamma= (const float*)d_in[15];
    const float* beta = (const float*)d_in[16];
    const float* Wm2  = (const float*)d_in[17];
    float* out = (float*)d_out;

    int n  = in_sizes[0] / D;
    int E0 = in_sizes[2];
    int E1 = in_sizes[4];

    float *pY, *phA, *phB, *pHcat, *pH1;
    cudaGetSymbolAddress((void**)&pY, g_Y);
    cudaGetSymbolAddress((void**)&phA, g_hA);
    cudaGetSymbolAddress((void**)&phB, g_hB);
    cudaGetSymbolAddress((void**)&pHcat, g_Hcat);
    cudaGetSymbolAddress((void**)&pH1, g_H1);

    int gbE0 = (E0 + 255) / 256, gbE1 = (E1 + 255) / 256;
    int gbN = (n + 255) / 256;
    int gbW = (n + 7) / 8;           // warp-per-node kernels, 256 thr
    int gbG = (n + 127) / 128;       // GEMM blocks

    k_zero<<<gbN, 256>>>(n);
    k_deg<<<gbE0, 256>>>(src0, dst0, 0, E0);
    k_deg<<<gbE1, 256>>>(src1, dst1, 1, E1);
    k_scan<<<1, 1024>>>(0, n);
    k_scan<<<1, 1024>>>(1, n);
    k_prep<<<gbN, 256>>>(n);
    k_fill<<<gbE0, 256>>>(src0, dst0, 0, E0);
    k_fill<<<gbE1, 256>>>(src1, dst1, 1, E1);

    // conv1: hB = relu(agg_r0(xA@W1_0)+b), hA = relu(agg_r1(xB@W1_1)+b)
    k_gemm<<<gbG, 256>>>(xA, W1_0, pY, n, 128, 128, 128);
    k_agg<<<gbW, 256>>>(pY, 0, b1_0, phB, n, 128, 1);
    k_gemm<<<gbG, 256>>>(xB, W1_1, pY, n, 128, 128, 128);
    k_agg<<<gbW, 256>>>(pY, 1, b1_1, phA, n, 128, 1);

    // conv2 -> concat buffer [h2A | h2B]
    k_gemm<<<gbG, 256>>>(phA, W2_0, pY, n, 128, 128, 128);
    k_agg<<<gbW, 256>>>(pY, 0, b2_0, pHcat + 128, n, 256, 0);   // h2B cols 128..255
    k_gemm<<<gbG, 256>>>(phB, W2_1, pY, n, 128, 128, 128);
    k_agg<<<gbW, 256>>>(pY, 1, b2_1, pHcat, n, 256, 0);         // h2A cols 0..127

    // MLP head
    k_gemm<<<gbG, 256>>>(pHcat, Wm1, pH1, n, 256, 256, 128);
    k_bnstats<<<256, 128>>>(pH1, n);
    k_bnfinal<<<1, 128>>>(gamma, beta, n);
    k_head<<<gbW, 256>>>(pH1, Wm2, out, n);
}

// round 5
// speedup vs baseline: 1.3245x; 1.3245x over previous
#include <cuda_runtime.h>
#include <cuda_bf16.h>
#include <cstdint>

#define NMAX 50000
#define EMAX 600000
#define D 128

// ---------------- scratch (device globals; no runtime allocation) ------------
__device__ int   g_deg[4][NMAX];        // [0]=outdeg r0, [1]=indeg r0, [2]=outdeg r1, [3]=indeg r1
__device__ int   g_rowptr[2][NMAX + 1];
__device__ int   g_cursor[2][NMAX];
__device__ int   g_col[2][EMAX];
__device__ int   g_bsum[2][256];        // per-block sums for multiblock scan
__device__ float g_srcscale[2][NMAX];
__device__ float g_Y[(size_t)NMAX * D];
__device__ float g_hA[(size_t)NMAX * D];
__device__ float g_hB[(size_t)NMAX * D];
__device__ float g_Hcat[(size_t)NMAX * 2 * D];
__device__ float g_H1[(size_t)NMAX * D];
__device__ float g_stats[2 * D];        // colsum, colsumsq
__device__ float g_aff[2 * D];          // a (scale), b (shift)

// ---------------- packed f32x2 helpers (Blackwell) ---------------------------
__device__ __forceinline__ unsigned long long pack2(float x, float y) {
    unsigned long long r;
    asm("mov.b64 %0, {%1, %2};" : "=l"(r) : "f"(x), "f"(y));
    return r;
}
__device__ __forceinline__ void ffma2(unsigned long long& d, unsigned long long a,
                                      unsigned long long b) {
    asm("fma.rn.f32x2 %0, %1, %2, %0;" : "+l"(d) : "l"(a), "l"(b));
}
__device__ __forceinline__ float2 unpack2(unsigned long long v) {
    float2 r;
    asm("mov.b64 {%0, %1}, %2;" : "=f"(r.x), "=f"(r.y) : "l"(v));
    return r;
}

// ---------------- graph build ------------------------------------------------
__global__ void k_zero(int n) {
    int i = blockIdx.x * blockDim.x + threadIdx.x;
    if (i < n) {
        g_deg[0][i] = 0; g_deg[1][i] = 0; g_deg[2][i] = 0; g_deg[3][i] = 0;
    }
    if (i < 2 * D) g_stats[i] = 0.0f;
}

__global__ void k_deg2(const int* __restrict__ s0, const int* __restrict__ d0, int E0,
                       const int* __restrict__ s1, const int* __restrict__ d1, int E1) {
    int e = blockIdx.x * blockDim.x + threadIdx.x;
    if (e < E0) {
        atomicAdd(&g_deg[0][s0[e]], 1);
        atomicAdd(&g_deg[1][d0[e]], 1);
    }
    if (e < E1) {
        atomicAdd(&g_deg[2][s1[e]], 1);
        atomicAdd(&g_deg[3][d1[e]], 1);
    }
}

// multiblock scan phase 1: per-block sums of indeg (256 elems/block, rel = blockIdx.y)
__global__ void k_scan1(int n) {
    int rel = blockIdx.y;
    int t = threadIdx.x;
    int i = blockIdx.x * 256 + t;
    int v = (i < n) ? g_deg[rel * 2 + 1][i] : 0;
#pragma unroll
    for (int o = 16; o > 0; o >>= 1) v += __shfl_down_sync(0xffffffffu, v, o);
    __shared__ int ws[8];
    if ((t & 31) == 0) ws[t >> 5] = v;
    __syncthreads();
    if (t == 0) {
        int s = 0;
#pragma unroll
        for (int j = 0; j < 8; ++j) s += ws[j];
        g_bsum[rel][blockIdx.x] = s;
    }
}

// phase 2: block offset = sum of prior block sums; shuffle block-scan of chunk;
// also init cursor and srcscale (folds old k_prep).
__global__ void k_scan2(int n) {
    int rel = blockIdx.y;
    int blk = blockIdx.x;
    int t = threadIdx.x;
    int lane = t & 31, wid = t >> 5;

    __shared__ int ws[8];
    __shared__ int s_off;
    __shared__ int wtot[8];

    // offset across prior blocks
    int p = 0;
    for (int j = t; j < blk; j += 256) p += g_bsum[rel][j];
#pragma unroll
    for (int o = 16; o > 0; o >>= 1) p += __shfl_down_sync(0xffffffffu, p, o);
    if (lane == 0) ws[wid] = p;
    __syncthreads();
    if (t == 0) {
        int s = 0;
#pragma unroll
        for (int j = 0; j < 8; ++j) s += ws[j];
        s_off = s;
    }
    __syncthreads();
    int offset = s_off;

    // inclusive scan of this block's 256 counts
    int i = blk * 256 + t;
    int v = (i < n) ? g_deg[rel * 2 + 1][i] : 0;
    int x = v;
#pragma unroll
    for (int o = 1; o < 32; o <<= 1) {
        int y = __shfl_up_sync(0xffffffffu, x, o);
        if (lane >= o) x += y;
    }
    if (lane == 31) wtot[wid] = x;
    __syncthreads();
    int add = 0;
#pragma unroll
    for (int j = 0; j < 8; ++j) add += (j < wid) ? wtot[j] : 0;
    int incl = x + add;

    if (i < n) {
        int start = offset + incl - v;
        g_rowptr[rel][i] = start;
        g_cursor[rel][i] = start;
        int od = g_deg[rel * 2][i];
        g_srcscale[rel][i] = rsqrtf((float)(od > 0 ? od : 1));
        if (i == n - 1) g_rowptr[rel][n] = offset + incl;
    }
}

__global__ void k_fill2(const int* __restrict__ s0, const int* __restrict__ d0, int E0,
                        const int* __restrict__ s1, const int* __restrict__ d1, int E1) {
    int e = blockIdx.x * blockDim.x + threadIdx.x;
    if (e < E0) {
        int p = atomicAdd(&g_cursor[0][d0[e]], 1);
        g_col[0][p] = s0[e];
    }
    if (e < E1) {
        int p = atomicAdd(&g_cursor[1][d1[e]], 1);
        g_col[1][p] = s1[e];
    }
}

// ---------------- aggregation: out[dst] = relu?( rsqrt(din)*sum_e s[src]*Y[src] + b )
__global__ void k_agg(const float* __restrict__ Y, int rel,
                      const float* __restrict__ bias, float* __restrict__ out,
                      int n, int ldc, int relu) {
    int warp = (blockIdx.x * blockDim.x + threadIdx.x) >> 5;
    int lane = threadIdx.x & 31;
    if (warp >= n) return;
    const int* __restrict__ rowptr = g_rowptr[rel];
    const int* __restrict__ col = g_col[rel];
    const float* __restrict__ ss = g_srcscale[rel];
    int s = rowptr[warp], e = rowptr[warp + 1];
    float4 acc = make_float4(0.f, 0.f, 0.f, 0.f);
    const float4* Y4 = (const float4*)Y;
    for (int i = s; i < e; ++i) {
        int src = __ldg(col + i);
        float w = __ldg(ss + src);
        float4 v = __ldg(Y4 + (size_t)src * 32 + lane);
        acc.x += w * v.x; acc.y += w * v.y; acc.z += w * v.z; acc.w += w * v.w;
    }
    int deg = e - s;
    float sc = rsqrtf((float)(deg > 0 ? deg : 1));
    float4 b = ((const float4*)bias)[lane];
    acc.x = acc.x * sc + b.x;
    acc.y = acc.y * sc + b.y;
    acc.z = acc.z * sc + b.z;
    acc.w = acc.w * sc + b.w;
    if (relu) {
        acc.x = fmaxf(acc.x, 0.f); acc.y = fmaxf(acc.y, 0.f);
        acc.z = fmaxf(acc.z, 0.f); acc.w = fmaxf(acc.w, 0.f);
    }
    *(float4*)(out + (size_t)warp * ldc + lane * 4) = acc;
}

// ---------------- GEMM: C[M,128] = A[M,K] @ W[K,128]  (fp32, f32x2 packed) ----
// block tile 128x128, 256 threads (16x16), per-thread 8x8, BK=16
__global__ __launch_bounds__(256) void k_gemm(const float* __restrict__ A,
                                              const float* __restrict__ W,
                                              float* __restrict__ C,
                                              int M, int K, int lda, int ldc) {
    __shared__ float As[16][128];   // transposed: As[k][m]
    __shared__ float Bs[16][128];   // Bs[k][n]
    int tid = threadIdx.x;
    int tx = tid & 15;      // col group
    int ty = tid >> 4;      // row group
    int rowBase = blockIdx.x * 128;

    unsigned long long acc[8][4];
#pragma unroll
    for (int r = 0; r < 8; ++r)
#pragma unroll
        for (int p = 0; p < 4; ++p) acc[r][p] = 0ull;

    for (int k0 = 0; k0 < K; k0 += 16) {
        // A tile: 128 rows x 16 k, as 512 float4 (row, 4k)
#pragma unroll
        for (int i = 0; i < 2; ++i) {
            int f4 = tid * 2 + i;          // 0..511
            int m = f4 >> 2;
            int kg = (f4 & 3) << 2;
            int gm = rowBase + m;
            float4 v = make_float4(0.f, 0.f, 0.f, 0.f);
            if (gm < M) v = *(const float4*)(A + (size_t)gm * lda + k0 + kg);
            As[kg + 0][m] = v.x; As[kg + 1][m] = v.y;
            As[kg + 2][m] = v.z; As[kg + 3][m] = v.w;
        }
        // B tile: 16 x 128 floats = 512 float4
#pragma unroll
        for (int i = 0; i < 2; ++i) {
            int f4 = tid * 2 + i;          // 0..511
            int kt = f4 >> 5;
            int n4 = (f4 & 31) << 2;
            float4 v = *(const float4*)(W + (size_t)(k0 + kt) * 128 + n4);
            *(float4*)&Bs[kt][n4] = v;
        }
        __syncthreads();
#pragma unroll
        for (int kk = 0; kk < 16; ++kk) {
            float a[8];
            *(float4*)(a + 0) = *(const float4*)&As[kk][ty * 8];
            *(float4*)(a + 4) = *(const float4*)&As[kk][ty * 8 + 4];
            float4 b0 = *(const float4*)&Bs[kk][tx * 8];
            float4 b1 = *(const float4*)&Bs[kk][tx * 8 + 4];
            unsigned long long bp[4];
            bp[0] = pack2(b0.x, b0.y); bp[1] = pack2(b0.z, b0.w);
            bp[2] = pack2(b1.x, b1.y); bp[3] = pack2(b1.z, b1.w);
#pragma unroll
            for (int r = 0; r < 8; ++r) {
                unsigned long long a2 = pack2(a[r], a[r]);
                ffma2(acc[r][0], a2, bp[0]);
                ffma2(acc[r][1], a2, bp[1]);
                ffma2(acc[r][2], a2, bp[2]);
                ffma2(acc[r][3], a2, bp[3]);
            }
        }
        __syncthreads();
    }

#pragma unroll
    for (int r = 0; r < 8; ++r) {
        int gm = rowBase + ty * 8 + r;
        if (gm < M) {
            float2 p0 = unpack2(acc[r][0]), p1 = unpack2(acc[r][1]);
            float2 p2 = unpack2(acc[r][2]), p3 = unpack2(acc[r][3]);
            float4 o0 = make_float4(p0.x, p0.y, p1.x, p1.y);
            float4 o1 = make_float4(p2.x, p2.y, p3.x, p3.y);
            *(float4*)(C + (size_t)gm * ldc + tx * 8)     = o0;
            *(float4*)(C + (size_t)gm * ldc + tx * 8 + 4) = o1;
        }
    }
}

// ---------------- BN stats / finalize / fused head ---------------------------
__global__ void k_bnstats(const float* __restrict__ H, int M) {
    int c = threadIdx.x;              // 128 threads, one column each
    int rows_per_block = (M + gridDim.x - 1) / gridDim.x;
    int r0 = blockIdx.x * rows_per_block;
    int r1 = r0 + rows_per_block; if (r1 > M) r1 = M;
    float s = 0.f, q = 0.f;
    for (int r = r0; r < r1; ++r) {
        float v = H[(size_t)r * D + c];
        s += v; q += v * v;
    }
    atomicAdd(&g_stats[c], s);
    atomicAdd(&g_stats[D + c], q);
}

__global__ void k_bnfinal(const float* __restrict__ gamma,
                          const float* __restrict__ beta, int M) {
    int c = threadIdx.x;
    float invM = 1.0f / (float)M;
    float mu = g_stats[c] * invM;
    float var = g_stats[D + c] * invM - mu * mu;
    float a = gamma[c] * rsqrtf(var + 1e-5f);
    g_aff[c] = a;
    g_aff[D + c] = beta[c] - mu * a;
}

__global__ void k_head(const float* __restrict__ H, const float* __restrict__ Wm2,
                       float* __restrict__ out, int n) {
    int warp = (blockIdx.x * blockDim.x + threadIdx.x) >> 5;
    int lane = threadIdx.x & 31;
    if (warp >= n) return;
    float4 h = ((const float4*)(H + (size_t)warp * D))[lane];
    float4 a = ((const float4*)g_aff)[lane];
    float4 b = ((const float4*)(g_aff + D))[lane];
    float v0 = fmaxf(h.x * a.x + b.x, 0.f);
    float v1 = fmaxf(h.y * a.y + b.y, 0.f);
    float v2 = fmaxf(h.z * a.z + b.z, 0.f);
    float v3 = fmaxf(h.w * a.w + b.w, 0.f);
    // Wm2 is [128][2] row-major; lane covers cols 4l..4l+3 -> 8 consecutive floats
    float4 wA = __ldg((const float4*)Wm2 + lane * 2 + 0); // {W[4l][0],W[4l][1],W[4l+1][0],W[4l+1][1]}
    float4 wB = __ldg((const float4*)Wm2 + lane * 2 + 1);
    float s0 = v0 * wA.x + v1 * wA.z + v2 * wB.x + v3 * wB.z;
    float s1 = v0 * wA.y + v1 * wA.w + v2 * wB.y + v3 * wB.w;
#pragma unroll
    for (int off = 16; off > 0; off >>= 1) {
        s0 += __shfl_down_sync(0xffffffffu, s0, off);
        s1 += __shfl_down_sync(0xffffffffu, s1, off);
    }
    if (lane == 0) {
        out[(size_t)warp * 2 + 0] = s0;
        out[(size_t)warp * 2 + 1] = s1;
    }
}

// ---------------- launch -----------------------------------------------------
extern "C" void kernel_launch(void* const* d_in, const int* in_sizes, int n_in,
                              void* d_out, int out_size) {
    const float* xA   = (const float*)d_in[0];
    const float* xB   = (const float*)d_in[1];
    const int* src0   = (const int*)d_in[2];
    const int* dst0   = (const int*)d_in[3];
    const int* src1   = (const int*)d_in[4];
    const int* dst1   = (const int*)d_in[5];
    const float* W1_0 = (const float*)d_in[6];
    const float* b1_0 = (const float*)d_in[7];
    const float* W1_1 = (const float*)d_in[8];
    const float* b1_1 = (const float*)d_in[9];
    const float* W2_0 = (const float*)d_in[10];
    const float* b2_0 = (const float*)d_in[11];
    const float* W2_1 = (const float*)d_in[12];
    const float* b2_1 = (const float*)d_in[13];
    const float* Wm1  = (const float*)d_in[14];
    const float* gamma= (const float*)d_in[15];
    const float* beta = (const float*)d_in[16];
    const float* Wm2  = (const float*)d_in[17];
    float* out = (float*)d_out;

    int n  = in_sizes[0] / D;
    int E0 = in_sizes[2];
    int E1 = in_sizes[4];
    int Emax = E0 > E1 ? E0 : E1;

    float *pY, *phA, *phB, *pHcat, *pH1;
    cudaGetSymbolAddress((void**)&pY, g_Y);
    cudaGetSymbolAddress((void**)&phA, g_hA);
    cudaGetSymbolAddress((void**)&phB, g_hB);
    cudaGetSymbolAddress((void**)&pHcat, g_Hcat);
    cudaGetSymbolAddress((void**)&pH1, g_H1);

    int gbE = (Emax + 255) / 256;
    int gbN = (n + 255) / 256;
    int gbW = (n + 7) / 8;           // warp-per-node kernels, 256 thr
    int gbG = (n + 127) / 128;       // GEMM blocks
    int scanBlocks = (n + 255) / 256;   // <= 256 for n <= 65536

    k_zero<<<gbN, 256>>>(n);
    k_deg2<<<gbE, 256>>>(src0, dst0, E0, src1, dst1, E1);
    k_scan1<<<dim3(scanBlocks, 2), 256>>>(n);
    k_scan2<<<dim3(scanBlocks, 2), 256>>>(n);
    k_fill2<<<gbE, 256>>>(src0, dst0, E0, src1, dst1, E1);

    // conv1: hB = relu(agg_r0(xA@W1_0)+b), hA = relu(agg_r1(xB@W1_1)+b)
    k_gemm<<<gbG, 256>>>(xA, W1_0, pY, n, 128, 128, 128);
    k_agg<<<gbW, 256>>>(pY, 0, b1_0, phB, n, 128, 1);
    k_gemm<<<gbG, 256>>>(xB, W1_1, pY, n, 128, 128, 128);
    k_agg<<<gbW, 256>>>(pY, 1, b1_1, phA, n, 128, 1);

    // conv2 -> concat buffer [h2A | h2B]
    k_gemm<<<gbG, 256>>>(phA, W2_0, pY, n, 128, 128, 128);
    k_agg<<<gbW, 256>>>(pY, 0, b2_0, pHcat + 128, n, 256, 0);   // h2B cols 128..255
    k_gemm<<<gbG, 256>>>(phB, W2_1, pY, n, 128, 128, 128);
    k_agg<<<gbW, 256>>>(pY, 1, b2_1, pHcat, n, 256, 0);         // h2A cols 0..127

    // MLP head
    k_gemm<<<gbG, 256>>>(pHcat, Wm1, pH1, n, 256, 256, 128);
    k_bnstats<<<256, 128>>>(pH1, n);
    k_bnfinal<<<1, 128>>>(gamma, beta, n);
    k_head<<<gbW, 256>>>(pH1, Wm2, out, n);
}

// round 7
// speedup vs baseline: 1.5031x; 1.1349x over previous
#include <cuda_runtime.h>
#include <cuda_bf16.h>
#include <cstdint>

#define NMAX 50000
#define EMAX 600000
#define D 128

// ---------------- scratch (device globals; no runtime allocation) ------------
__device__ int   g_deg[4][NMAX];
__device__ int   g_rowptr[2][NMAX + 1];
__device__ int   g_cursor[2][NMAX];
__device__ int   g_col[2][EMAX];
__device__ int   g_bsum[2][256];
__device__ float g_srcscale[2][NMAX];
__device__ float g_Y0[(size_t)NMAX * D];
__device__ float g_Y1[(size_t)NMAX * D];
__device__ float g_hA[(size_t)NMAX * D];
__device__ float g_hB[(size_t)NMAX * D];
__device__ float g_Hcat[(size_t)NMAX * 2 * D];
__device__ float g_H1[(size_t)NMAX * D];
__device__ float g_stats[2 * D];
__device__ float g_aff[2 * D];

// ---------------- streams/events (created pre-main; no device-mem delta) -----
struct HxStreams {
    cudaStream_t sB{}, sC{};
    cudaEvent_t evStart{}, evBuild{}, evC{};
    HxStreams() {
        cudaStreamCreateWithFlags(&sB, cudaStreamNonBlocking);
        cudaStreamCreateWithFlags(&sC, cudaStreamNonBlocking);
        cudaEventCreateWithFlags(&evStart, cudaEventDisableTiming);
        cudaEventCreateWithFlags(&evBuild, cudaEventDisableTiming);
        cudaEventCreateWithFlags(&evC, cudaEventDisableTiming);
    }
};
static HxStreams g_hx;

// ---------------- packed f32x2 helpers (Blackwell) ---------------------------
__device__ __forceinline__ unsigned long long pack2(float x, float y) {
    unsigned long long r;
    asm("mov.b64 %0, {%1, %2};" : "=l"(r) : "f"(x), "f"(y));
    return r;
}
__device__ __forceinline__ void ffma2(unsigned long long& d, unsigned long long a,
                                      unsigned long long b) {
    asm("fma.rn.f32x2 %0, %1, %2, %0;" : "+l"(d) : "l"(a), "l"(b));
}
__device__ __forceinline__ float2 unpack2(unsigned long long v) {
    float2 r;
    asm("mov.b64 {%0, %1}, %2;" : "=f"(r.x), "=f"(r.y) : "l"(v));
    return r;
}

// ---------------- graph build ------------------------------------------------
__global__ void k_zero(int n) {
    int i = blockIdx.x * blockDim.x + threadIdx.x;
    if (i < n) {
        g_deg[0][i] = 0; g_deg[1][i] = 0; g_deg[2][i] = 0; g_deg[3][i] = 0;
    }
    if (i < 2 * D) g_stats[i] = 0.0f;
}

__global__ void k_deg2(const int* __restrict__ s0, const int* __restrict__ d0, int E0,
                       const int* __restrict__ s1, const int* __restrict__ d1, int E1) {
    int e = blockIdx.x * blockDim.x + threadIdx.x;
    if (e < E0) {
        atomicAdd(&g_deg[0][s0[e]], 1);
        atomicAdd(&g_deg[1][d0[e]], 1);
    }
    if (e < E1) {
        atomicAdd(&g_deg[2][s1[e]], 1);
        atomicAdd(&g_deg[3][d1[e]], 1);
    }
}

__global__ void k_scan1(int n) {
    int rel = blockIdx.y;
    int t = threadIdx.x;
    int i = blockIdx.x * 256 + t;
    int v = (i < n) ? g_deg[rel * 2 + 1][i] : 0;
#pragma unroll
    for (int o = 16; o > 0; o >>= 1) v += __shfl_down_sync(0xffffffffu, v, o);
    __shared__ int ws[8];
    if ((t & 31) == 0) ws[t >> 5] = v;
    __syncthreads();
    if (t == 0) {
        int s = 0;
#pragma unroll
        for (int j = 0; j < 8; ++j) s += ws[j];
        g_bsum[rel][blockIdx.x] = s;
    }
}

__global__ void k_scan2(int n) {
    int rel = blockIdx.y;
    int blk = blockIdx.x;
    int t = threadIdx.x;
    int lane = t & 31, wid = t >> 5;

    __shared__ int ws[8];
    __shared__ int s_off;
    __shared__ int wtot[8];

    int p = 0;
    for (int j = t; j < blk; j += 256) p += g_bsum[rel][j];
#pragma unroll
    for (int o = 16; o > 0; o >>= 1) p += __shfl_down_sync(0xffffffffu, p, o);
    if (lane == 0) ws[wid] = p;
    __syncthreads();
    if (t == 0) {
        int s = 0;
#pragma unroll
        for (int j = 0; j < 8; ++j) s += ws[j];
        s_off = s;
    }
    __syncthreads();
    int offset = s_off;

    int i = blk * 256 + t;
    int v = (i < n) ? g_deg[rel * 2 + 1][i] : 0;
    int x = v;
#pragma unroll
    for (int o = 1; o < 32; o <<= 1) {
        int y = __shfl_up_sync(0xffffffffu, x, o);
        if (lane >= o) x += y;
    }
    if (lane == 31) wtot[wid] = x;
    __syncthreads();
    int add = 0;
#pragma unroll
    for (int j = 0; j < 8; ++j) add += (j < wid) ? wtot[j] : 0;
    int incl = x + add;

    if (i < n) {
        int start = offset + incl - v;
        g_rowptr[rel][i] = start;
        g_cursor[rel][i] = start;
        int od = g_deg[rel * 2][i];
        g_srcscale[rel][i] = rsqrtf((float)(od > 0 ? od : 1));
        if (i == n - 1) g_rowptr[rel][n] = offset + incl;
    }
}

__global__ void k_fill2(const int* __restrict__ s0, const int* __restrict__ d0, int E0,
                        const int* __restrict__ s1, const int* __restrict__ d1, int E1) {
    int e = blockIdx.x * blockDim.x + threadIdx.x;
    if (e < E0) {
        int p = atomicAdd(&g_cursor[0][d0[e]], 1);
        g_col[0][p] = s0[e];
    }
    if (e < E1) {
        int p = atomicAdd(&g_cursor[1][d1[e]], 1);
        g_col[1][p] = s1[e];
    }
}

// ---------------- aggregation ------------------------------------------------
__global__ void k_agg(const float* __restrict__ Y, int rel,
                      const float* __restrict__ bias, float* __restrict__ out,
                      int n, int ldc, int relu) {
    int warp = (blockIdx.x * blockDim.x + threadIdx.x) >> 5;
    int lane = threadIdx.x & 31;
    if (warp >= n) return;
    const int* __restrict__ rowptr = g_rowptr[rel];
    const int* __restrict__ col = g_col[rel];
    const float* __restrict__ ss = g_srcscale[rel];
    int s = rowptr[warp], e = rowptr[warp + 1];
    float4 acc = make_float4(0.f, 0.f, 0.f, 0.f);
    const float4* Y4 = (const float4*)Y;
    for (int i = s; i < e; ++i) {
        int src = __ldg(col + i);
        float w = __ldg(ss + src);
        float4 v = __ldg(Y4 + (size_t)src * 32 + lane);
        acc.x += w * v.x; acc.y += w * v.y; acc.z += w * v.z; acc.w += w * v.w;
    }
    int deg = e - s;
    float sc = rsqrtf((float)(deg > 0 ? deg : 1));
    float4 b = ((const float4*)bias)[lane];
    acc.x = acc.x * sc + b.x;
    acc.y = acc.y * sc + b.y;
    acc.z = acc.z * sc + b.z;
    acc.w = acc.w * sc + b.w;
    if (relu) {
        acc.x = fmaxf(acc.x, 0.f); acc.y = fmaxf(acc.y, 0.f);
        acc.z = fmaxf(acc.z, 0.f); acc.w = fmaxf(acc.w, 0.f);
    }
    *(float4*)(out + (size_t)warp * ldc + lane * 4) = acc;
}

// ---------------- GEMM: C[M,128] = A[M,K] @ W[K,128]  (fp32, f32x2 packed) ----
__global__ __launch_bounds__(256) void k_gemm(const float* __restrict__ A,
                                              const float* __restrict__ W,
                                              float* __restrict__ C,
                                              int M, int K, int lda, int ldc) {
    __shared__ float As[16][128];   // As[k][m]
    __shared__ float Bs[16][128];   // Bs[k][n]
    int tid = threadIdx.x;
    int tx = tid & 15;
    int ty = tid >> 4;
    int rowBase = blockIdx.x * 128;

    unsigned long long acc[8][4];
#pragma unroll
    for (int r = 0; r < 8; ++r)
#pragma unroll
        for (int p = 0; p < 4; ++p) acc[r][p] = 0ull;

    for (int k0 = 0; k0 < K; k0 += 16) {
#pragma unroll
        for (int i = 0; i < 2; ++i) {
            int f4 = tid * 2 + i;
            int m = f4 >> 2;
            int kg = (f4 & 3) << 2;
            int gm = rowBase + m;
            float4 v = make_float4(0.f, 0.f, 0.f, 0.f);
            if (gm < M) v = *(const float4*)(A + (size_t)gm * lda + k0 + kg);
            As[kg + 0][m] = v.x; As[kg + 1][m] = v.y;
            As[kg + 2][m] = v.z; As[kg + 3][m] = v.w;
        }
#pragma unroll
        for (int i = 0; i < 2; ++i) {
            int f4 = tid * 2 + i;
            int kt = f4 >> 5;
            int n4 = (f4 & 31) << 2;
            float4 v = *(const float4*)(W + (size_t)(k0 + kt) * 128 + n4);
            *(float4*)&Bs[kt][n4] = v;
        }
        __syncthreads();
#pragma unroll
        for (int kk = 0; kk < 16; ++kk) {
            float a[8];
            *(float4*)(a + 0) = *(const float4*)&As[kk][ty * 8];
            *(float4*)(a + 4) = *(const float4*)&As[kk][ty * 8 + 4];
            // b pairs read directly as packed u64 (register pairs) — no pack MOVs
            ulonglong2 q0 = *(const ulonglong2*)&Bs[kk][tx * 8];
            ulonglong2 q1 = *(const ulonglong2*)&Bs[kk][tx * 8 + 4];
#pragma unroll
            for (int r = 0; r < 8; ++r) {
                unsigned long long a2 = pack2(a[r], a[r]);
                ffma2(acc[r][0], a2, q0.x);
                ffma2(acc[r][1], a2, q0.y);
                ffma2(acc[r][2], a2, q1.x);
                ffma2(acc[r][3], a2, q1.y);
            }
        }
        __syncthreads();
    }

#pragma unroll
    for (int r = 0; r < 8; ++r) {
        int gm = rowBase + ty * 8 + r;
        if (gm < M) {
            float2 p0 = unpack2(acc[r][0]), p1 = unpack2(acc[r][1]);
            float2 p2 = unpack2(acc[r][2]), p3 = unpack2(acc[r][3]);
            float4 o0 = make_float4(p0.x, p0.y, p1.x, p1.y);
            float4 o1 = make_float4(p2.x, p2.y, p3.x, p3.y);
            *(float4*)(C + (size_t)gm * ldc + tx * 8)     = o0;
            *(float4*)(C + (size_t)gm * ldc + tx * 8 + 4) = o1;
        }
    }
}

// ---------------- BN stats / finalize / fused head ---------------------------
__global__ void k_bnstats(const float* __restrict__ H, int M) {
    int c = threadIdx.x;
    int rows_per_block = (M + gridDim.x - 1) / gridDim.x;
    int r0 = blockIdx.x * rows_per_block;
    int r1 = r0 + rows_per_block; if (r1 > M) r1 = M;
    float s = 0.f, q = 0.f;
    for (int r = r0; r < r1; ++r) {
        float v = H[(size_t)r * D + c];
        s += v; q += v * v;
    }
    atomicAdd(&g_stats[c], s);
    atomicAdd(&g_stats[D + c], q);
}

__global__ void k_bnfinal(const float* __restrict__ gamma,
                          const float* __restrict__ beta, int M) {
    int c = threadIdx.x;
    float invM = 1.0f / (float)M;
    float mu = g_stats[c] * invM;
    float var = g_stats[D + c] * invM - mu * mu;
    float a = gamma[c] * rsqrtf(var + 1e-5f);
    g_aff[c] = a;
    g_aff[D + c] = beta[c] - mu * a;
}

__global__ void k_head(const float* __restrict__ H, const float* __restrict__ Wm2,
                       float* __restrict__ out, int n) {
    int warp = (blockIdx.x * blockDim.x + threadIdx.x) >> 5;
    int lane = threadIdx.x & 31;
    if (warp >= n) return;
    float4 h = ((const float4*)(H + (size_t)warp * D))[lane];
    float4 a = ((const float4*)g_aff)[lane];
    float4 b = ((const float4*)(g_aff + D))[lane];
    float v0 = fmaxf(h.x * a.x + b.x, 0.f);
    float v1 = fmaxf(h.y * a.y + b.y, 0.f);
    float v2 = fmaxf(h.z * a.z + b.z, 0.f);
    float v3 = fmaxf(h.w * a.w + b.w, 0.f);
    float4 wA = __ldg((const float4*)Wm2 + lane * 2 + 0);
    float4 wB = __ldg((const float4*)Wm2 + lane * 2 + 1);
    float s0 = v0 * wA.x + v1 * wA.z + v2 * wB.x + v3 * wB.z;
    float s1 = v0 * wA.y + v1 * wA.w + v2 * wB.y + v3 * wB.w;
#pragma unroll
    for (int off = 16; off > 0; off >>= 1) {
        s0 += __shfl_down_sync(0xffffffffu, s0, off);
        s1 += __shfl_down_sync(0xffffffffu, s1, off);
    }
    if (lane == 0) {
        out[(size_t)warp * 2 + 0] = s0;
        out[(size_t)warp * 2 + 1] = s1;
    }
}

// ---------------- launch -----------------------------------------------------
extern "C" void kernel_launch(void* const* d_in, const int* in_sizes, int n_in,
                              void* d_out, int out_size) {
    const float* xA   = (const float*)d_in[0];
    const float* xB   = (const float*)d_in[1];
    const int* src0   = (const int*)d_in[2];
    const int* dst0   = (const int*)d_in[3];
    const int* src1   = (const int*)d_in[4];
    const int* dst1   = (const int*)d_in[5];
    const float* W1_0 = (const float*)d_in[6];
    const float* b1_0 = (const float*)d_in[7];
    const float* W1_1 = (const float*)d_in[8];
    const float* b1_1 = (const float*)d_in[9];
    const float* W2_0 = (const float*)d_in[10];
    const float* b2_0 = (const float*)d_in[11];
    const float* W2_1 = (const float*)d_in[12];
    const float* b2_1 = (const float*)d_in[13];
    const float* Wm1  = (const float*)d_in[14];
    const float* gamma= (const float*)d_in[15];
    const float* beta = (const float*)d_in[16];
    const float* Wm2  = (const float*)d_in[17];
    float* out = (float*)d_out;

    int n  = in_sizes[0] / D;
    int E0 = in_sizes[2];
    int E1 = in_sizes[4];
    int Emax = E0 > E1 ? E0 : E1;

    float *pY0, *pY1, *phA, *phB, *pHcat, *pH1;
    cudaGetSymbolAddress((void**)&pY0, g_Y0);
    cudaGetSymbolAddress((void**)&pY1, g_Y1);
    cudaGetSymbolAddress((void**)&phA, g_hA);
    cudaGetSymbolAddress((void**)&phB, g_hB);
    cudaGetSymbolAddress((void**)&pHcat, g_Hcat);
    cudaGetSymbolAddress((void**)&pH1, g_H1);

    int gbE = (Emax + 255) / 256;
    int gbN = (n + 255) / 256;
    int gbW = (n + 7) / 8;
    int gbG = (n + 127) / 128;
    int scanBlocks = (n + 255) / 256;

    cudaStream_t s0 = 0;                 // capture stream (legacy default)
    cudaStream_t sB = g_hx.sB, sC = g_hx.sC;

    // fork
    cudaEventRecord(g_hx.evStart, s0);
    cudaStreamWaitEvent(sB, g_hx.evStart, 0);
    cudaStreamWaitEvent(sC, g_hx.evStart, 0);

    // graph build on sB (overlaps with conv1 GEMMs)
    k_zero<<<gbN, 256, 0, sB>>>(n);
    k_deg2<<<gbE, 256, 0, sB>>>(src0, dst0, E0, src1, dst1, E1);
    k_scan1<<<dim3(scanBlocks, 2), 256, 0, sB>>>(n);
    k_scan2<<<dim3(scanBlocks, 2), 256, 0, sB>>>(n);
    k_fill2<<<gbE, 256, 0, sB>>>(src0, dst0, E0, src1, dst1, E1);
    cudaEventRecord(g_hx.evBuild, sB);

    // chain A on s0: xA@W1_0 -> agg r0 -> hB -> hB@W2_1 -> agg r1 -> Hcat[:,0:128]
    k_gemm<<<gbG, 256, 0, s0>>>(xA, W1_0, pY0, n, 128, 128, 128);
    cudaStreamWaitEvent(s0, g_hx.evBuild, 0);
    k_agg<<<gbW, 256, 0, s0>>>(pY0, 0, b1_0, phB, n, 128, 1);
    k_gemm<<<gbG, 256, 0, s0>>>(phB, W2_1, pY0, n, 128, 128, 128);
    k_agg<<<gbW, 256, 0, s0>>>(pY0, 1, b2_1, pHcat, n, 256, 0);

    // chain B on sC: xB@W1_1 -> agg r1 -> hA -> hA@W2_0 -> agg r0 -> Hcat[:,128:256]
    k_gemm<<<gbG, 256, 0, sC>>>(xB, W1_1, pY1, n, 128, 128, 128);
    cudaStreamWaitEvent(sC, g_hx.evBuild, 0);
    k_agg<<<gbW, 256, 0, sC>>>(pY1, 1, b1_1, phA, n, 128, 1);
    k_gemm<<<gbG, 256, 0, sC>>>(phA, W2_0, pY1, n, 128, 128, 128);
    k_agg<<<gbW, 256, 0, sC>>>(pY1, 0, b2_0, pHcat + 128, n, 256, 0);
    cudaEventRecord(g_hx.evC, sC);

    // join + MLP head on s0
    cudaStreamWaitEvent(s0, g_hx.evC, 0);
    k_gemm<<<gbG, 256, 0, s0>>>(pHcat, Wm1, pH1, n, 256, 256, 128);
    k_bnstats<<<256, 128, 0, s0>>>(pH1, n);
    k_bnfinal<<<1, 128, 0, s0>>>(gamma, beta, n);
    k_head<<<gbW, 256, 0, s0>>>(pH1, Wm2, out, n);
}